// round 13
// baseline (speedup 1.0000x reference)
#include <cuda_runtime.h>
#include <cuda_bf16.h>
#include <cstdint>

// Table-batched embedding bag, SUM pooling.
// inputs (metadata order):
//   d_in[0] indices          int32 or int64  [T*B*L]
//   d_in[1] offsets          int32 or int64  [T*B + 1]   (CSR bag offsets)
//   d_in[2] weights          fp32            [T*E, D]    (stacked tables)
//   d_in[3] hash_size_cumsum int32 or int64  [T + 1]
// output: fp32 [B, T*D]   (bag g = t*B + b  ->  out[b, t*D : (t+1)*D])
//
// dtype sniff (JAX downcasts int64->int32 by default): offsets strictly
// increase from 0, so ((const int*)offsets)[1]==0 <=> int64 data.
//
// CONVERGED (R8/R10/R11/R12 plateau 57.8 +/- 0.3us, HBM ~5.7TB/s =
// random-512B-gather DRAM ceiling; traffic at model minimum). Best-measured
// configuration, resubmitted unchanged: one warp per bag, cp.async ring
// (6 slots, 12KB/block), AHEAD=5, 128 threads/block, 16 blocks/SM
// (64 warps), st.cs output, __ldg indices.

#define FULL_MASK 0xFFFFFFFFu

__device__ __forceinline__ void cp_async16(uint32_t smem_addr, const void* gptr) {
    asm volatile("cp.async.cg.shared.global [%0], [%1], 16;\n"
                 :: "r"(smem_addr), "l"(gptr));
}
__device__ __forceinline__ void cp_commit() {
    asm volatile("cp.async.commit_group;\n" ::: "memory");
}
template <int N>
__device__ __forceinline__ void cp_wait() {
    asm volatile("cp.async.wait_group %0;\n" :: "n"(N) : "memory");
}
__device__ __forceinline__ void stcs128(float4* p, float4 v) {
    asm volatile("st.global.cs.v4.f32 [%0], {%1,%2,%3,%4};\n"
                 :: "l"(p), "f"(v.x), "f"(v.y), "f"(v.z), "f"(v.w) : "memory");
}

// ring: [4 warps][6 slots][32 lanes] float4 = 12 KB per 128-thread block
#define WARPS_PER_BLOCK 4
#define SLOTS 6
#define AHEAD 5   // rows in flight per warp (AHEAD < SLOTS)

template <typename IdxT>
__device__ __forceinline__
void bag_pipe(const IdxT* __restrict__ indices,
              const IdxT* __restrict__ offsets,
              const float* __restrict__ weights,
              const IdxT* __restrict__ hash_cumsum,
              float* __restrict__ out,
              uint32_t smem_warp_base,                 // byte addr of warp ring
              const float4* __restrict__ ring_warp,    // generic ptr, same region
              int bag, int batch, int n_tables, int lane) {
    const int table = bag / batch;          // feature-major bag layout
    const int b     = bag - table * batch;

    const int start = (int)offsets[bag];
    const int count = (int)offsets[bag + 1] - start;
    const int base  = (int)hash_cumsum[table];   // < 4M rows, fits int32

    const float4* __restrict__ w4 = (const float4*)weights;

    // Preload up to 32 bag indices, one per lane (single coalesced load).
    int myidx = 0;
    if (lane < count) myidx = (int)__ldg(&indices[start + lane]);

    // Prologue: issue first AHEAD rows into slots 0..AHEAD-1.
    #pragma unroll
    for (int p = 0; p < AHEAD; ++p) {
        if (p < count) {
            const int r = __shfl_sync(FULL_MASK, myidx, p) + base;
            cp_async16(smem_warp_base + (uint32_t)((p * 32 + lane) << 4),
                       (const void*)&w4[(long long)r * 32 + lane]);
        }
        cp_commit();
    }

    // Ring counters (SLOTS is not a power of two).
    int rs = 0;                 // read slot for iteration j
    int ws = AHEAD;             // write slot for row j+AHEAD  (AHEAD < SLOTS)

    float4 acc = make_float4(0.f, 0.f, 0.f, 0.f);
    for (int j = 0; j < count; ++j) {
        cp_wait<AHEAD - 1>();   // group j complete -> slot rs ready
        const float4 v = ring_warp[rs * 32 + lane];
        const int nj = j + AHEAD;
        if (nj < count) {
            int r;
            if (nj < 32) r = __shfl_sync(FULL_MASK, myidx, nj) + base;
            else         r = (int)__ldg(&indices[start + nj]) + base;
            cp_async16(smem_warp_base + (uint32_t)((ws * 32 + lane) << 4),
                       (const void*)&w4[(long long)r * 32 + lane]);
        }
        cp_commit();
        acc.x += v.x; acc.y += v.y; acc.z += v.z; acc.w += v.w;
        rs = (rs + 1 == SLOTS) ? 0 : rs + 1;
        ws = (ws + 1 == SLOTS) ? 0 : ws + 1;
    }
    cp_wait<0>();   // drain trailing empty groups

    // evict-first store: write-once output, keep L2 for table rows
    stcs128(((float4*)out) + ((long long)b * n_tables + table) * 32 + lane, acc);
}

__global__ __launch_bounds__(128, 16)
void tbe_fwd_d128_kernel(const void* __restrict__ indices_raw,
                         const void* __restrict__ offsets_raw,
                         const float* __restrict__ weights,
                         const void* __restrict__ hash_cumsum_raw,
                         float* __restrict__ out,
                         int num_bags, int batch, int n_tables) {
    __shared__ __align__(16) float4 ring[WARPS_PER_BLOCK * SLOTS * 32];  // 12 KB

    const int warp = threadIdx.x >> 5;
    const int lane = threadIdx.x & 31;
    const int bag  = blockIdx.x * WARPS_PER_BLOCK + warp;
    if (bag >= num_bags) return;

    float4* ring_warp = &ring[warp * SLOTS * 32];
    const uint32_t smem_warp_base =
        (uint32_t)__cvta_generic_to_shared(ring_warp);

    // dtype sniff: offsets strictly increasing from 0 (uniform branch)
    const bool is64 = (((const int*)offsets_raw)[1] == 0);

    if (is64) {
        bag_pipe<long long>((const long long*)indices_raw,
                            (const long long*)offsets_raw,
                            weights,
                            (const long long*)hash_cumsum_raw,
                            out, smem_warp_base, ring_warp,
                            bag, batch, n_tables, lane);
    } else {
        bag_pipe<int>((const int*)indices_raw,
                      (const int*)offsets_raw,
                      weights,
                      (const int*)hash_cumsum_raw,
                      out, smem_warp_base, ring_warp,
                      bag, batch, n_tables, lane);
    }
}

// Generic fallback for D != 128: one thread per output element (int32 idx).
template <typename IdxT>
__global__ void tbe_fwd_generic_kernel(const IdxT* __restrict__ indices,
                                       const IdxT* __restrict__ offsets,
                                       const float* __restrict__ weights,
                                       const IdxT* __restrict__ hash_cumsum,
                                       float* __restrict__ out,
                                       int num_bags, int batch, int n_tables,
                                       int D) {
    long long gid = (long long)blockIdx.x * blockDim.x + threadIdx.x;
    long long total = (long long)num_bags * D;
    if (gid >= total) return;
    int bag = (int)(gid / D);
    int d   = (int)(gid - (long long)bag * D);
    int table = bag / batch;
    int b     = bag - table * batch;
    long long start = (long long)offsets[bag];
    long long end   = (long long)offsets[bag + 1];
    long long base  = (long long)hash_cumsum[table];
    float acc = 0.f;
    for (long long j = start; j < end; ++j) {
        long long row = (long long)indices[j] + base;
        acc += weights[row * D + d];
    }
    out[((long long)b * n_tables + table) * D + d] = acc;
}

extern "C" void kernel_launch(void* const* d_in, const int* in_sizes, int n_in,
                              void* d_out, int out_size) {
    const void*  indices     = d_in[0];
    const void*  offsets     = d_in[1];
    const float* weights     = (const float*)d_in[2];
    const void*  hash_cumsum = d_in[3];
    float* out = (float*)d_out;

    const int num_bags = in_sizes[1] - 1;        // T*B
    const int n_tables = in_sizes[3] - 1;        // T
    const int batch    = num_bags / n_tables;    // B
    const int D        = out_size / num_bags;    // 128 expected

    if (D == 128) {
        const int grid = (num_bags + WARPS_PER_BLOCK - 1) / WARPS_PER_BLOCK;
        tbe_fwd_d128_kernel<<<grid, 128>>>(indices, offsets, weights,
                                           hash_cumsum, out,
                                           num_bags, batch, n_tables);
    } else {
        long long total = (long long)num_bags * D;
        int grid = (int)((total + 255) / 256);
        tbe_fwd_generic_kernel<int><<<grid, 256>>>(
            (const int*)indices, (const int*)offsets, weights,
            (const int*)hash_cumsum, out, num_bags, batch, n_tables, D);
    }
}

// round 14
// speedup vs baseline: 1.0111x; 1.0111x over previous
#include <cuda_runtime.h>
#include <cuda_bf16.h>
#include <cstdint>

// Table-batched embedding bag, SUM pooling.
// inputs (metadata order):
//   d_in[0] indices          int32 or int64  [T*B*L]
//   d_in[1] offsets          int32 or int64  [T*B + 1]   (CSR bag offsets)
//   d_in[2] weights          fp32            [T*E, D]    (stacked tables)
//   d_in[3] hash_size_cumsum int32 or int64  [T + 1]
// output: fp32 [B, T*D]   (bag g = t*B + b  ->  out[b, t*D : (t+1)*D])
//
// dtype sniff (JAX downcasts int64->int32 by default): offsets strictly
// increase from 0, so ((const int*)offsets)[1]==0 <=> int64 data.
//
// CONVERGED at the hardware roofline (R8/R10/R11/R12/R13: 57.8 +/- 0.3us,
// HBM 5.6-5.7TB/s = random-512B-gather DRAM ceiling; traffic at model
// minimum; occupancy/depth/granularity all verified non-binding).
// Best-measured configuration, resubmitted unchanged: one warp per bag,
// cp.async ring (6 slots, 12KB/block), AHEAD=5, 128 threads/block,
// 16 blocks/SM (64 warps), st.cs output, __ldg indices.

#define FULL_MASK 0xFFFFFFFFu

__device__ __forceinline__ void cp_async16(uint32_t smem_addr, const void* gptr) {
    asm volatile("cp.async.cg.shared.global [%0], [%1], 16;\n"
                 :: "r"(smem_addr), "l"(gptr));
}
__device__ __forceinline__ void cp_commit() {
    asm volatile("cp.async.commit_group;\n" ::: "memory");
}
template <int N>
__device__ __forceinline__ void cp_wait() {
    asm volatile("cp.async.wait_group %0;\n" :: "n"(N) : "memory");
}
__device__ __forceinline__ void stcs128(float4* p, float4 v) {
    asm volatile("st.global.cs.v4.f32 [%0], {%1,%2,%3,%4};\n"
                 :: "l"(p), "f"(v.x), "f"(v.y), "f"(v.z), "f"(v.w) : "memory");
}

// ring: [4 warps][6 slots][32 lanes] float4 = 12 KB per 128-thread block
#define WARPS_PER_BLOCK 4
#define SLOTS 6
#define AHEAD 5   // rows in flight per warp (AHEAD < SLOTS)

template <typename IdxT>
__device__ __forceinline__
void bag_pipe(const IdxT* __restrict__ indices,
              const IdxT* __restrict__ offsets,
              const float* __restrict__ weights,
              const IdxT* __restrict__ hash_cumsum,
              float* __restrict__ out,
              uint32_t smem_warp_base,                 // byte addr of warp ring
              const float4* __restrict__ ring_warp,    // generic ptr, same region
              int bag, int batch, int n_tables, int lane) {
    const int table = bag / batch;          // feature-major bag layout
    const int b     = bag - table * batch;

    const int start = (int)offsets[bag];
    const int count = (int)offsets[bag + 1] - start;
    const int base  = (int)hash_cumsum[table];   // < 4M rows, fits int32

    const float4* __restrict__ w4 = (const float4*)weights;

    // Preload up to 32 bag indices, one per lane (single coalesced load).
    int myidx = 0;
    if (lane < count) myidx = (int)__ldg(&indices[start + lane]);

    // Prologue: issue first AHEAD rows into slots 0..AHEAD-1.
    #pragma unroll
    for (int p = 0; p < AHEAD; ++p) {
        if (p < count) {
            const int r = __shfl_sync(FULL_MASK, myidx, p) + base;
            cp_async16(smem_warp_base + (uint32_t)((p * 32 + lane) << 4),
                       (const void*)&w4[(long long)r * 32 + lane]);
        }
        cp_commit();
    }

    // Ring counters (SLOTS is not a power of two).
    int rs = 0;                 // read slot for iteration j
    int ws = AHEAD;             // write slot for row j+AHEAD  (AHEAD < SLOTS)

    float4 acc = make_float4(0.f, 0.f, 0.f, 0.f);
    for (int j = 0; j < count; ++j) {
        cp_wait<AHEAD - 1>();   // group j complete -> slot rs ready
        const float4 v = ring_warp[rs * 32 + lane];
        const int nj = j + AHEAD;
        if (nj < count) {
            int r;
            if (nj < 32) r = __shfl_sync(FULL_MASK, myidx, nj) + base;
            else         r = (int)__ldg(&indices[start + nj]) + base;
            cp_async16(smem_warp_base + (uint32_t)((ws * 32 + lane) << 4),
                       (const void*)&w4[(long long)r * 32 + lane]);
        }
        cp_commit();
        acc.x += v.x; acc.y += v.y; acc.z += v.z; acc.w += v.w;
        rs = (rs + 1 == SLOTS) ? 0 : rs + 1;
        ws = (ws + 1 == SLOTS) ? 0 : ws + 1;
    }
    cp_wait<0>();   // drain trailing empty groups

    // evict-first store: write-once output, keep L2 for table rows
    stcs128(((float4*)out) + ((long long)b * n_tables + table) * 32 + lane, acc);
}

__global__ __launch_bounds__(128, 16)
void tbe_fwd_d128_kernel(const void* __restrict__ indices_raw,
                         const void* __restrict__ offsets_raw,
                         const float* __restrict__ weights,
                         const void* __restrict__ hash_cumsum_raw,
                         float* __restrict__ out,
                         int num_bags, int batch, int n_tables) {
    __shared__ __align__(16) float4 ring[WARPS_PER_BLOCK * SLOTS * 32];  // 12 KB

    const int warp = threadIdx.x >> 5;
    const int lane = threadIdx.x & 31;
    const int bag  = blockIdx.x * WARPS_PER_BLOCK + warp;
    if (bag >= num_bags) return;

    float4* ring_warp = &ring[warp * SLOTS * 32];
    const uint32_t smem_warp_base =
        (uint32_t)__cvta_generic_to_shared(ring_warp);

    // dtype sniff: offsets strictly increasing from 0 (uniform branch)
    const bool is64 = (((const int*)offsets_raw)[1] == 0);

    if (is64) {
        bag_pipe<long long>((const long long*)indices_raw,
                            (const long long*)offsets_raw,
                            weights,
                            (const long long*)hash_cumsum_raw,
                            out, smem_warp_base, ring_warp,
                            bag, batch, n_tables, lane);
    } else {
        bag_pipe<int>((const int*)indices_raw,
                      (const int*)offsets_raw,
                      weights,
                      (const int*)hash_cumsum_raw,
                      out, smem_warp_base, ring_warp,
                      bag, batch, n_tables, lane);
    }
}

// Generic fallback for D != 128: one thread per output element (int32 idx).
template <typename IdxT>
__global__ void tbe_fwd_generic_kernel(const IdxT* __restrict__ indices,
                                       const IdxT* __restrict__ offsets,
                                       const float* __restrict__ weights,
                                       const IdxT* __restrict__ hash_cumsum,
                                       float* __restrict__ out,
                                       int num_bags, int batch, int n_tables,
                                       int D) {
    long long gid = (long long)blockIdx.x * blockDim.x + threadIdx.x;
    long long total = (long long)num_bags * D;
    if (gid >= total) return;
    int bag = (int)(gid / D);
    int d   = (int)(gid - (long long)bag * D);
    int table = bag / batch;
    int b     = bag - table * batch;
    long long start = (long long)offsets[bag];
    long long end   = (long long)offsets[bag + 1];
    long long base  = (long long)hash_cumsum[table];
    float acc = 0.f;
    for (long long j = start; j < end; ++j) {
        long long row = (long long)indices[j] + base;
        acc += weights[row * D + d];
    }
    out[((long long)b * n_tables + table) * D + d] = acc;
}

extern "C" void kernel_launch(void* const* d_in, const int* in_sizes, int n_in,
                              void* d_out, int out_size) {
    const void*  indices     = d_in[0];
    const void*  offsets     = d_in[1];
    const float* weights     = (const float*)d_in[2];
    const void*  hash_cumsum = d_in[3];
    float* out = (float*)d_out;

    const int num_bags = in_sizes[1] - 1;        // T*B
    const int n_tables = in_sizes[3] - 1;        // T
    const int batch    = num_bags / n_tables;    // B
    const int D        = out_size / num_bags;    // 128 expected

    if (D == 128) {
        const int grid = (num_bags + WARPS_PER_BLOCK - 1) / WARPS_PER_BLOCK;
        tbe_fwd_d128_kernel<<<grid, 128>>>(indices, offsets, weights,
                                           hash_cumsum, out,
                                           num_bags, batch, n_tables);
    } else {
        long long total = (long long)num_bags * D;
        int grid = (int)((total + 255) / 256);
        tbe_fwd_generic_kernel<int><<<grid, 256>>>(
            (const int*)indices, (const int*)offsets, weights,
            (const int*)hash_cumsum, out, num_bags, batch, n_tables, D);
    }
}